// round 2
// baseline (speedup 1.0000x reference)
#include <cuda_runtime.h>
#include <cuda_bf16.h>
#include <cstddef>

#define LEAK 0.2f
#define BS 4
#define NSTK 32
#define NPNT 256
#define NPT 8192           // NSTK*NPNT
#define CIN 96
#define SPIN 64
#define DNIN 32
#define MIDDN 110
#define DNOUT 64
#define MIDSP 156
#define SPOUT 128
#define KDN 50

// ---------------- scratch (allocation-free rule: __device__ globals) ----------------
__device__ float g_xt[(size_t)BS * NPT * CIN];       // point-major fused dense features
__device__ float g_x2[BS * NPT];
__device__ float g_D[(size_t)BS * NPT * NPT];        // 1 GiB distance matrix
__device__ int   g_knn[(size_t)BS * NPT * KDN];
__device__ float g_A[(size_t)BS * NPT * MIDDN];      // x @ W1a^T
__device__ float g_B[(size_t)BS * NPT * MIDDN];      // x @ (W1b-W1a)^T + b1
__device__ float g_dnfeat[(size_t)BS * DNOUT * NPT]; // channel-major GCN output
__device__ float g_xs[BS * NSTK * CIN];              // fused sparse features, point-major

__device__ __forceinline__ float lrelu(float v) { return v > 0.f ? v : LEAK * v; }

// ---------------- build fused dense features + squared norms ----------------
__global__ void k_build_xt(const float* __restrict__ dense, const float* __restrict__ sparse) {
    int bn = blockIdx.x;            // b*NPT + n
    int b = bn >> 13, n = bn & (NPT - 1);
    int s = n >> 8, p = n & 255;
    int t = threadIdx.x;            // 96
    float v;
    if (t < DNIN) v = dense[(((size_t)(b * DNIN + t) * NSTK + s) << 8) + p];
    else          v = sparse[(b * SPIN + (t - DNIN)) * NSTK + s];
    g_xt[(size_t)bn * CIN + t] = v;
    __shared__ float red[CIN];
    red[t] = v * v;
    __syncthreads();
    if (t < 32) {
        float s2 = red[t] + red[t + 32] + red[t + 64];
        for (int o = 16; o > 0; o >>= 1) s2 += __shfl_down_sync(0xffffffffu, s2, o);
        if (t == 0) g_x2[bn] = s2;
    }
}

// ---------------- sparse fused features: max over points, and copy sparse ----------------
__global__ void k_spdn(const float* __restrict__ dense) {
    int idx = blockIdx.x;           // (b, c, s)
    int b = idx >> 10, c = (idx >> 5) & 31, s = idx & 31;
    int t = threadIdx.x;            // 256
    float v = dense[(((size_t)(b * DNIN + c) * NSTK + s) << 8) + t];
    __shared__ float red[256];
    red[t] = v;
    __syncthreads();
    for (int o = 128; o >= 32; o >>= 1) { if (t < o) red[t] = fmaxf(red[t], red[t + o]); __syncthreads(); }
    if (t < 32) {
        float m = red[t];
        for (int o = 16; o > 0; o >>= 1) m = fmaxf(m, __shfl_down_sync(0xffffffffu, m, o));
        if (t == 0) g_xs[(b * NSTK + s) * CIN + SPIN + c] = m;
    }
}
__global__ void k_xs_sp(const float* __restrict__ sparse) {
    int bs_ = blockIdx.x;           // b*NSTK+s
    int b = bs_ >> 5, s = bs_ & 31;
    int t = threadIdx.x;            // 64
    g_xs[(b * NSTK + s) * CIN + t] = sparse[(b * SPIN + t) * NSTK + s];
}

// ---------------- pairwise squared distances: D = x2_i + x2_j - 2 * X X^T ----------------
__global__ void __launch_bounds__(256) k_dist() {
    int b = blockIdx.z;
    int i0 = blockIdx.y * 64, j0 = blockIdx.x * 64;
    const float* X = g_xt + (size_t)b * NPT * CIN;
    const float* x2 = g_x2 + b * NPT;
    __shared__ float As[32][65];
    __shared__ float Bs[32][65];
    int t = threadIdx.x;
    int tx = t & 15, ty = t >> 4;
    float acc[4][4];
#pragma unroll
    for (int u = 0; u < 4; u++)
#pragma unroll
        for (int v = 0; v < 4; v++) acc[u][v] = 0.f;

    for (int k0 = 0; k0 < CIN; k0 += 32) {
        __syncthreads();
#pragma unroll
        for (int r = 0; r < 8; r++) {
            int ii = (t >> 5) + r * 8;
            int k = t & 31;
            As[k][ii] = X[(size_t)(i0 + ii) * CIN + k0 + k];
            Bs[k][ii] = X[(size_t)(j0 + ii) * CIN + k0 + k];
        }
        __syncthreads();
#pragma unroll
        for (int k = 0; k < 32; k++) {
            float a0 = As[k][ty * 4 + 0], a1 = As[k][ty * 4 + 1], a2 = As[k][ty * 4 + 2], a3 = As[k][ty * 4 + 3];
            float b0 = Bs[k][tx * 4 + 0], b1 = Bs[k][tx * 4 + 1], b2 = Bs[k][tx * 4 + 2], b3 = Bs[k][tx * 4 + 3];
            acc[0][0] += a0 * b0; acc[0][1] += a0 * b1; acc[0][2] += a0 * b2; acc[0][3] += a0 * b3;
            acc[1][0] += a1 * b0; acc[1][1] += a1 * b1; acc[1][2] += a1 * b2; acc[1][3] += a1 * b3;
            acc[2][0] += a2 * b0; acc[2][1] += a2 * b1; acc[2][2] += a2 * b2; acc[2][3] += a2 * b3;
            acc[3][0] += a3 * b0; acc[3][1] += a3 * b1; acc[3][2] += a3 * b2; acc[3][3] += a3 * b3;
        }
    }
    float x2j0 = x2[j0 + tx * 4 + 0], x2j1 = x2[j0 + tx * 4 + 1], x2j2 = x2[j0 + tx * 4 + 2], x2j3 = x2[j0 + tx * 4 + 3];
#pragma unroll
    for (int u = 0; u < 4; u++) {
        float xi = x2[i0 + ty * 4 + u];
        float4 w;
        w.x = xi + x2j0 - 2.f * acc[u][0];
        w.y = xi + x2j1 - 2.f * acc[u][1];
        w.z = xi + x2j2 - 2.f * acc[u][2];
        w.w = xi + x2j3 - 2.f * acc[u][3];
        *(float4*)&g_D[((size_t)b * NPT + i0 + ty * 4 + u) * NPT + j0 + tx * 4] = w;
    }
}

// ---------------- top-50 smallest per row via radix select in SMEM ----------------
__global__ void __launch_bounds__(256) k_topk() {
    int row = blockIdx.x;           // b*NPT + i
    const float* Drow = g_D + (size_t)row * NPT;
    __shared__ unsigned key[NPT];
    __shared__ int hist[256];
    __shared__ unsigned sh_pref;
    __shared__ int sh_kk, sh_cless, sh_tiecnt;
    __shared__ int tielist[256];
    int t = threadIdx.x;
    for (int j = t; j < NPT; j += 256) {
        unsigned u = __float_as_uint(Drow[j]);
        key[j] = (u & 0x80000000u) ? ~u : (u | 0x80000000u);
    }
    if (t == 0) { sh_pref = 0u; sh_kk = KDN; }
    __syncthreads();
    for (int pass = 0; pass < 4; ++pass) {
        int shift = 24 - pass * 8;
        hist[t] = 0;
        __syncthreads();
        unsigned pref = sh_pref;
        for (int j = t; j < NPT; j += 256) {
            unsigned kx = key[j];
            if (pass == 0 || (kx >> (shift + 8)) == pref)
                atomicAdd(&hist[(kx >> shift) & 255], 1);
        }
        __syncthreads();
        if (t == 0) {
            int kk = sh_kk, c = 0, bsel = 0;
            for (int bin = 0; bin < 256; bin++) {
                int h = hist[bin];
                if (c + h >= kk) { bsel = bin; kk -= c; break; }
                c += h;
            }
            sh_kk = kk;
            sh_pref = (pref << 8) | (unsigned)bsel;
        }
        __syncthreads();
    }
    unsigned T = sh_pref;           // full key of the 50th smallest
    if (t == 0) { sh_cless = 0; sh_tiecnt = 0; }
    __syncthreads();
    int* out = g_knn + (size_t)row * KDN;
    for (int j = t; j < NPT; j += 256) {
        unsigned kx = key[j];
        if (kx < T) { int pos = atomicAdd(&sh_cless, 1); out[pos] = j; }
        else if (kx == T) { int p = atomicAdd(&sh_tiecnt, 1); if (p < 256) tielist[p] = j; }
    }
    __syncthreads();
    if (t == 0) {
        int c = sh_cless;
        int need = KDN - c;
        int m = sh_tiecnt < 256 ? sh_tiecnt : 256;
        for (int a = 1; a < m; a++) {           // ascending index = jax stable tie-break
            int v = tielist[a], bdx = a - 1;
            while (bdx >= 0 && tielist[bdx] > v) { tielist[bdx + 1] = tielist[bdx]; bdx--; }
            tielist[bdx + 1] = v;
        }
        for (int a = 0; a < need; a++) out[c + a] = tielist[a];
    }
}

// ---------------- A = x@W1a^T ; B = x@(W1b-W1a)^T + b1 (layer-1 factorization) ----------------
#define ABPITCH 97
__global__ void __launch_bounds__(256) k_AB(const float* __restrict__ W1, const float* __restrict__ b1) {
    extern __shared__ float sm[];
    float* Wa = sm;                           // [110][97]
    float* Wd = sm + MIDDN * ABPITCH;         // [110][97]
    float* xs = sm + 2 * MIDDN * ABPITCH;     // [16][96]
    int t = threadIdx.x;
    for (int idx = t; idx < MIDDN * CIN; idx += 256) {
        int k = idx / CIN, c = idx % CIN;
        float wa = W1[k * (2 * CIN) + c];
        float wb = W1[k * (2 * CIN) + CIN + c];
        Wa[k * ABPITCH + c] = wa;
        Wd[k * ABPITCH + c] = wb - wa;
    }
    int p0 = blockIdx.x * 16;
    for (int idx = t; idx < 16 * CIN; idx += 256)
        xs[idx] = g_xt[(size_t)(p0 + idx / CIN) * CIN + (idx % CIN)];
    __syncthreads();
    for (int idx = t; idx < 16 * MIDDN; idx += 256) {
        int pp = idx / MIDDN, k = idx % MIDDN;
        const float* xr = xs + pp * CIN;
        float a = 0.f, bb = 0.f;
#pragma unroll
        for (int c = 0; c < CIN; c++) {
            float xv = xr[c];
            a += xv * Wa[k * ABPITCH + c];
            bb += xv * Wd[k * ABPITCH + c];
        }
        size_t off = (size_t)(p0 + pp) * MIDDN + k;
        g_A[off] = a;
        g_B[off] = bb + b1[k];
    }
}

// ---------------- per-edge layer-2 MLP + max over k neighbors ----------------
__global__ void __launch_bounds__(128) k_mlp(const float* __restrict__ W2, const float* __restrict__ b2) {
    __shared__ float W2t[MIDDN * 64];   // [k][c] transposed
    __shared__ float h1[MIDDN];
    __shared__ float Bp[MIDDN];
    __shared__ float part[64];
    int t = threadIdx.x;
    for (int idx = t; idx < MIDDN * 64; idx += 128) {
        int k = idx >> 6, c = idx & 63;
        W2t[idx] = W2[c * MIDDN + k];
    }
    int half = t >> 6, c = t & 63;
    float b2v = (half == 1) ? b2[c] : 0.f;
    int p0 = blockIdx.x * 8;
    for (int pi = 0; pi < 8; ++pi) {
        int n = p0 + pi;
        int b = n >> 13, ni = n & (NPT - 1);
        __syncthreads();
        if (t < MIDDN) Bp[t] = g_B[(size_t)n * MIDDN + t];
        const int* kn = g_knn + (size_t)n * KDN;
        float acc = -3.4e38f;
        for (int j = 0; j < KDN; ++j) {
            int nb = kn[j];
            __syncthreads();
            if (t < MIDDN) {
                float v = g_A[(size_t)(b * NPT + nb) * MIDDN + t] + Bp[t];
                h1[t] = lrelu(v);
            }
            __syncthreads();
            float s = 0.f;
            int k0 = half * 55;
#pragma unroll
            for (int k = 0; k < 55; k++) s += W2t[(k0 + k) * 64 + c] * h1[k0 + k];
            if (!half) part[c] = s;
            __syncthreads();
            if (half) acc = fmaxf(acc, lrelu(part[c] + s + b2v));
        }
        if (half) g_dnfeat[(size_t)(b * DNOUT + c) * NPT + ni] = acc;
    }
}

// ---------------- sparse GCN (k=2 over 32 strokes) ----------------
__global__ void __launch_bounds__(192) k_sparse(const float* __restrict__ W1, const float* __restrict__ b1,
                                                const float* __restrict__ W2, const float* __restrict__ b2,
                                                float* __restrict__ out) {
    int bi = blockIdx.x;
    int b = bi >> 5, i = bi & 31;
    __shared__ float xi[CIN];
    __shared__ float d[NSTK];
    __shared__ float h1[MIDSP];
    __shared__ int nbr2[2];
    const float* Xs = g_xs + b * NSTK * CIN;
    int t = threadIdx.x;
    if (t < CIN) xi[t] = Xs[i * CIN + t];
    __syncthreads();
    if (t < NSTK) {
        float s = 0.f;
        for (int cc = 0; cc < CIN; cc++) { float dx = Xs[t * CIN + cc] - xi[cc]; s += dx * dx; }
        d[t] = s;
    }
    __syncthreads();
    if (t == 0) {
        int i1 = 0; float v1 = d[0];
        for (int j = 1; j < NSTK; j++) if (d[j] < v1) { v1 = d[j]; i1 = j; }
        int i2 = -1; float v2 = 3.4e38f;
        for (int j = 0; j < NSTK; j++) { if (j == i1) continue; if (d[j] < v2) { v2 = d[j]; i2 = j; } }
        nbr2[0] = i1; nbr2[1] = i2;
    }
    __syncthreads();
    float acc = -3.4e38f;
    for (int jj = 0; jj < 2; jj++) {
        int nb = nbr2[jj];
        __syncthreads();
        if (t < MIDSP) {
            float s = b1[t];
            const float* w = W1 + t * (2 * CIN);
            for (int cc = 0; cc < CIN; cc++) {
                float xj = Xs[nb * CIN + cc], xc = xi[cc];
                s += (xj - xc) * w[cc] + xc * w[CIN + cc];
            }
            h1[t] = lrelu(s);
        }
        __syncthreads();
        if (t < SPOUT) {
            float s = b2[t];
            const float* w = W2 + t * MIDSP;
            for (int k = 0; k < MIDSP; k++) s += w[k] * h1[k];
            acc = fmaxf(acc, lrelu(s));
        }
    }
    if (t < SPOUT) out[(b * SPOUT + t) * NSTK + i] = acc;
}

// ---------------- downsample conv (1,3)/stride(1,2)/pad(0,1) + leaky ----------------
__global__ void __launch_bounds__(256) k_down(const float* __restrict__ dsW, const float* __restrict__ dsb,
                                              float* __restrict__ out) {
    extern __shared__ float sm[];
    float* tile = sm;                 // [64][256]
    float* Wsh = sm + DNOUT * NPNT;   // [64][64][3]
    int bs_ = blockIdx.x;
    int b = bs_ >> 5, s = bs_ & 31;
    int t = threadIdx.x;
    for (int idx = t; idx < DNOUT * NPNT; idx += 256) {
        int ic = idx >> 8, p = idx & 255;
        tile[idx] = g_dnfeat[(size_t)(b * DNOUT + ic) * NPT + s * NPNT + p];
    }
    for (int idx = t; idx < DNOUT * DNOUT * 3; idx += 256) Wsh[idx] = dsW[idx];
    __syncthreads();
    const int QO = NPNT / 2;          // 128
    for (int idx = t; idx < DNOUT * QO; idx += 256) {
        int o = idx >> 7, q = idx & 127;
        float acc = dsb[o];
        int pbase = 2 * q - 1;
        const float* wrow = Wsh + o * (DNOUT * 3);
        for (int ic = 0; ic < DNOUT; ic++) {
            const float* tr = tile + ic * NPNT;
            float w0 = wrow[ic * 3 + 0], w1 = wrow[ic * 3 + 1], w2 = wrow[ic * 3 + 2];
            float a = 0.f;
            if (pbase >= 0) a += tr[pbase] * w0;
            a += tr[pbase + 1] * w1;
            if (pbase + 2 < NPNT) a += tr[pbase + 2] * w2;
            acc += a;
        }
        out[BS * SPOUT * NSTK + (((size_t)b * DNOUT + o) * NSTK + s) * QO + q] = lrelu(acc);
    }
}

extern "C" void kernel_launch(void* const* d_in, const int* in_sizes, int n_in,
                              void* d_out, int out_size) {
    const float* sparse = (const float*)d_in[0];
    const float* dense  = (const float*)d_in[1];
    const float* spW1 = (const float*)d_in[2];
    const float* spb1 = (const float*)d_in[3];
    const float* spW2 = (const float*)d_in[4];
    const float* spb2 = (const float*)d_in[5];
    const float* dnW1 = (const float*)d_in[6];
    const float* dnb1 = (const float*)d_in[7];
    const float* dnW2 = (const float*)d_in[8];
    const float* dnb2 = (const float*)d_in[9];
    const float* dsW  = (const float*)d_in[10];
    const float* dsb  = (const float*)d_in[11];
    float* out = (float*)d_out;

    const int AB_SMEM   = (2 * MIDDN * ABPITCH + 16 * CIN) * 4;          // ~91.5 KB
    const int DOWN_SMEM = (DNOUT * NPNT + DNOUT * DNOUT * 3) * 4;        // 112 KB
    cudaFuncSetAttribute(k_AB,   cudaFuncAttributeMaxDynamicSharedMemorySize, AB_SMEM);
    cudaFuncSetAttribute(k_down, cudaFuncAttributeMaxDynamicSharedMemorySize, DOWN_SMEM);

    k_build_xt<<<BS * NPT, CIN>>>(dense, sparse);
    k_spdn<<<BS * DNIN * NSTK, 256>>>(dense);
    k_xs_sp<<<BS * NSTK, SPIN>>>(sparse);
    k_dist<<<dim3(NPT / 64, NPT / 64, BS), 256>>>();
    k_topk<<<BS * NPT, 256>>>();
    k_AB<<<(BS * NPT) / 16, 256, AB_SMEM>>>(dnW1, dnb1);
    k_mlp<<<(BS * NPT) / 8, 128>>>(dnW2, dnb2);
    k_sparse<<<BS * NSTK, 192>>>(spW1, spb1, spW2, spb2, out);
    k_down<<<BS * NSTK, 256, DOWN_SMEM>>>(dsW, dsb, out);
}